// round 4
// baseline (speedup 1.0000x reference)
#include <cuda_runtime.h>
#include <cuda_bf16.h>
#include <cstdint>

// Problem constants
#define BDIM 2
#define TDIM 2048
#define CDIM 1024
#define HN   16
#define HD   64
#define MROWS (BDIM * TDIM)   // 4096
#define NQKV  (3 * CDIM)      // 3072
#define KDEPTH CDIM           // 1024

// Scratch
__device__ __align__(16) float g_Q[BDIM * HN * TDIM * HD];
__device__ __align__(16) float g_K[BDIM * HN * TDIM * HD];
__device__ __align__(16) float g_V[BDIM * HN * TDIM * HD];
__device__ __align__(16) float g_att[MROWS * CDIM];

// ---------------------------------------------------------------------------
// tf32 helpers
// ---------------------------------------------------------------------------
__device__ __forceinline__ uint32_t f2tf32(float x) {
    uint32_t r;
    asm("cvt.rna.tf32.f32 %0, %1;" : "=r"(r) : "f"(x));
    return r;
}

__device__ __forceinline__ void mma_tf32(float* d, const uint32_t* a, const uint32_t* b) {
    asm volatile(
        "mma.sync.aligned.m16n8k8.row.col.f32.tf32.tf32.f32 "
        "{%0,%1,%2,%3},{%4,%5,%6,%7},{%8,%9},{%0,%1,%2,%3};"
        : "+f"(d[0]), "+f"(d[1]), "+f"(d[2]), "+f"(d[3])
        : "r"(a[0]), "r"(a[1]), "r"(a[2]), "r"(a[3]), "r"(b[0]), "r"(b[1]));
}

// k-permutation within each group of 8 so that logical cols (c, c+4) sit at
// contiguous positions (2c, 2c+1): pos(k) = k<4 ? 2k : 2(k-4)+1
__device__ __forceinline__ int kperm(int kc) {
    return (kc & 4) ? ((kc & 3) * 2 + 1) : (kc * 2);
}

// Tile geometry: 128x128x16, 8 warps (2x4), warp tile 64x32
#define BM 128
#define BN 128
#define BK 16
#define SROW 24   // smem row stride in words (16 data + 8 pad -> conflict-free frags)

// ---------------------------------------------------------------------------
// Shared GEMM core: C[128x128] partial = A[128x1024] * W[1024x128-tile]
// A row-major [M,K], W row-major [K,N]. tf32 3-pass split. Accumulators out.
// ---------------------------------------------------------------------------
struct GemmAcc {
    float acc[4][4][4];  // [mf][nf][4]
};

template <int NLD>
__device__ __forceinline__ void gemm_tf32_body(
    const float* __restrict__ A, const float* __restrict__ W,
    int m0, int n0, GemmAcc& R,
    uint32_t* As_hi, uint32_t* As_lo, uint32_t* Bs_hi, uint32_t* Bs_lo)
{
    const int tid = threadIdx.x;
    const int lane = tid & 31;
    const int wid = tid >> 5;
    const int gid = lane >> 2;   // 0..7
    const int tg = lane & 3;     // 0..3
    const int warp_m0 = (wid >> 2) * 64;
    const int warp_n0 = (wid & 3) * 32;

#pragma unroll
    for (int mf = 0; mf < 4; mf++)
#pragma unroll
        for (int nf = 0; nf < 4; nf++)
#pragma unroll
            for (int e = 0; e < 4; e++) R.acc[mf][nf][e] = 0.f;

    for (int k0 = 0; k0 < KDEPTH; k0 += BK) {
        // ---- load + convert A tile: [128 rows][16 k] ----
#pragma unroll
        for (int p = 0; p < 2; p++) {
            int f = tid + p * 256;         // float4 id, 0..511
            int row = f >> 2;
            int c4 = f & 3;
            float4 v = *(const float4*)&A[(m0 + row) * KDEPTH + k0 + c4 * 4];
            float vv[4] = {v.x, v.y, v.z, v.w};
#pragma unroll
            for (int j = 0; j < 4; j++) {
                int col = c4 * 4 + j;
                int kk = (col >> 3) * 8 + kperm(col & 7);
                uint32_t h = f2tf32(vv[j]);
                As_hi[row * SROW + kk] = h;
                As_lo[row * SROW + kk] = f2tf32(vv[j] - __uint_as_float(h));
            }
        }
        // ---- load + convert B tile (transposed): Bs[n][kk] ----
#pragma unroll
        for (int p = 0; p < 2; p++) {
            int f = tid + p * 256;         // 0..511
            int kr = f >> 5;               // 0..15
            int c4 = f & 31;               // 0..31
            float4 v = *(const float4*)&W[(k0 + kr) * NLD + n0 + c4 * 4];
            float vv[4] = {v.x, v.y, v.z, v.w};
            int kk = (kr >> 3) * 8 + kperm(kr & 7);
#pragma unroll
            for (int j = 0; j < 4; j++) {
                int n = c4 * 4 + j;
                uint32_t h = f2tf32(vv[j]);
                Bs_hi[n * SROW + kk] = h;
                Bs_lo[n * SROW + kk] = f2tf32(vv[j] - __uint_as_float(h));
            }
        }
        __syncthreads();

        // ---- two k-steps of 8 ----
#pragma unroll
        for (int ks = 0; ks < 2; ks++) {
            uint32_t a_hi[4][4], a_lo[4][4], b_hi[4][2], b_lo[4][2];
#pragma unroll
            for (int mf = 0; mf < 4; mf++) {
                int r0 = warp_m0 + mf * 16 + gid;
                uint2 p0h = *(const uint2*)&As_hi[r0 * SROW + ks * 8 + 2 * tg];
                uint2 p1h = *(const uint2*)&As_hi[(r0 + 8) * SROW + ks * 8 + 2 * tg];
                uint2 p0l = *(const uint2*)&As_lo[r0 * SROW + ks * 8 + 2 * tg];
                uint2 p1l = *(const uint2*)&As_lo[(r0 + 8) * SROW + ks * 8 + 2 * tg];
                a_hi[mf][0] = p0h.x; a_hi[mf][1] = p1h.x; a_hi[mf][2] = p0h.y; a_hi[mf][3] = p1h.y;
                a_lo[mf][0] = p0l.x; a_lo[mf][1] = p1l.x; a_lo[mf][2] = p0l.y; a_lo[mf][3] = p1l.y;
            }
#pragma unroll
            for (int nf = 0; nf < 4; nf++) {
                int c = warp_n0 + nf * 8 + gid;
                uint2 qh = *(const uint2*)&Bs_hi[c * SROW + ks * 8 + 2 * tg];
                uint2 ql = *(const uint2*)&Bs_lo[c * SROW + ks * 8 + 2 * tg];
                b_hi[nf][0] = qh.x; b_hi[nf][1] = qh.y;
                b_lo[nf][0] = ql.x; b_lo[nf][1] = ql.y;
            }
#pragma unroll
            for (int mf = 0; mf < 4; mf++)
#pragma unroll
                for (int nf = 0; nf < 4; nf++) {
                    mma_tf32(R.acc[mf][nf], a_hi[mf], b_hi[nf]);
                    mma_tf32(R.acc[mf][nf], a_lo[mf], b_hi[nf]);
                    mma_tf32(R.acc[mf][nf], a_hi[mf], b_lo[nf]);
                }
        }
        __syncthreads();
    }
}

// ---------------------------------------------------------------------------
// GEMM 1: qkv = x @ Wqkv + bqkv ; scatter to Q/K/V (B,H,T,hd)
// ---------------------------------------------------------------------------
__global__ void __launch_bounds__(256, 1) gemm_qkv_kernel(
    const float* __restrict__ A,      // x    [4096,1024]
    const float* __restrict__ W,      // Wqkv [1024,3072]
    const float* __restrict__ bias)   // bqkv [3072]
{
    __shared__ uint32_t As_hi[BM * SROW], As_lo[BM * SROW];
    __shared__ uint32_t Bs_hi[BN * SROW], Bs_lo[BN * SROW];

    const int m0 = blockIdx.y * BM;
    const int n0 = blockIdx.x * BN;
    const int lane = threadIdx.x & 31;
    const int wid = threadIdx.x >> 5;
    const int gid = lane >> 2, tg = lane & 3;
    const int warp_m0 = (wid >> 2) * 64;
    const int warp_n0 = (wid & 3) * 32;

    GemmAcc R;
    gemm_tf32_body<NQKV>(A, W, m0, n0, R, As_hi, As_lo, Bs_hi, Bs_lo);

    // Epilogue: bias + scatter
#pragma unroll
    for (int mf = 0; mf < 4; mf++) {
#pragma unroll
        for (int nf = 0; nf < 4; nf++) {
#pragma unroll
            for (int e = 0; e < 4; e++) {
                int m = m0 + warp_m0 + mf * 16 + gid + ((e >> 1) ? 8 : 0);
                int n = n0 + warp_n0 + nf * 8 + 2 * tg + (e & 1);
                float c = R.acc[mf][nf][e] + bias[n];
                int bb = m >> 11;
                int t = m & 2047;
                int h = n / 192;
                int r = n - h * 192;
                int which = r >> 6;
                int d = r & 63;
                int idx = (((bb * HN + h) * TDIM) + t) * HD + d;
                if (which == 0)      g_Q[idx] = c;
                else if (which == 1) g_K[idx] = c;
                else                 g_V[idx] = c;
            }
        }
    }
}

// ---------------------------------------------------------------------------
// GEMM 2: out = att @ Wproj + bproj
// ---------------------------------------------------------------------------
__global__ void __launch_bounds__(256, 1) gemm_proj_kernel(
    const float* __restrict__ W,      // Wproj [1024,1024]
    const float* __restrict__ bias,   // bproj [1024]
    float* __restrict__ out)          // [4096,1024]
{
    __shared__ uint32_t As_hi[BM * SROW], As_lo[BM * SROW];
    __shared__ uint32_t Bs_hi[BN * SROW], Bs_lo[BN * SROW];

    const int m0 = blockIdx.y * BM;
    const int n0 = blockIdx.x * BN;
    const int lane = threadIdx.x & 31;
    const int wid = threadIdx.x >> 5;
    const int gid = lane >> 2, tg = lane & 3;
    const int warp_m0 = (wid >> 2) * 64;
    const int warp_n0 = (wid & 3) * 32;

    GemmAcc R;
    gemm_tf32_body<CDIM>(g_att, W, m0, n0, R, As_hi, As_lo, Bs_hi, Bs_lo);

#pragma unroll
    for (int mf = 0; mf < 4; mf++) {
#pragma unroll
        for (int nf = 0; nf < 4; nf++) {
#pragma unroll
            for (int e = 0; e < 4; e++) {
                int m = m0 + warp_m0 + mf * 16 + gid + ((e >> 1) ? 8 : 0);
                int n = n0 + warp_n0 + nf * 8 + 2 * tg + (e & 1);
                out[m * CDIM + n] = R.acc[mf][nf][e] + bias[n];
            }
        }
    }
}

// ---------------------------------------------------------------------------
// Flash attention (fp32, causal) — unchanged from validated baseline
// ---------------------------------------------------------------------------
__global__ void __launch_bounds__(256) attn_kernel()
{
    __shared__ __align__(16) float QsT[64][64];
    __shared__ __align__(16) float KsT[64][64];
    __shared__ __align__(16) float Vs[64][64];

    const int tid = threadIdx.x;
    const int tx = tid & 15;
    const int ty = tid >> 4;
    const int qtile = blockIdx.x;
    const int h = blockIdx.y;
    const int b = blockIdx.z;

    const float* Qb = g_Q + (((b * HN + h) * TDIM) + qtile * 64) * HD;
    const float* Kb = g_K + ((b * HN + h) * TDIM) * HD;
    const float* Vb = g_V + ((b * HN + h) * TDIM) * HD;

    {
        int row = tid >> 2;
        int d0 = (tid & 3) * 16;
#pragma unroll
        for (int v = 0; v < 4; v++) {
            float4 q4 = *(const float4*)&Qb[row * HD + d0 + v * 4];
            QsT[d0 + v * 4 + 0][row] = q4.x;
            QsT[d0 + v * 4 + 1][row] = q4.y;
            QsT[d0 + v * 4 + 2][row] = q4.z;
            QsT[d0 + v * 4 + 3][row] = q4.w;
        }
    }

    float m_i[4], l_i[4], o_acc[4][4];
#pragma unroll
    for (int i = 0; i < 4; i++) {
        m_i[i] = -1e30f;
        l_i[i] = 0.f;
#pragma unroll
        for (int j = 0; j < 4; j++) o_acc[i][j] = 0.f;
    }

    float (*Ps)[64] = (float (*)[64])KsT;

    for (int kt = 0; kt <= qtile; kt++) {
        __syncthreads();
        {
            int row = tid >> 2;
            int d0 = (tid & 3) * 16;
            const float* Kp = Kb + (kt * 64 + row) * HD;
            const float* Vp = Vb + (kt * 64 + row) * HD;
#pragma unroll
            for (int v = 0; v < 4; v++) {
                float4 k4 = *(const float4*)&Kp[d0 + v * 4];
                KsT[d0 + v * 4 + 0][row] = k4.x;
                KsT[d0 + v * 4 + 1][row] = k4.y;
                KsT[d0 + v * 4 + 2][row] = k4.z;
                KsT[d0 + v * 4 + 3][row] = k4.w;
                *(float4*)&Vs[row][d0 + v * 4] = *(const float4*)&Vp[d0 + v * 4];
            }
        }
        __syncthreads();

        float s[4][4] = {};
#pragma unroll
        for (int d = 0; d < 64; d++) {
            float4 a4 = *(const float4*)&QsT[d][ty * 4];
            float4 b4 = *(const float4*)&KsT[d][tx * 4];
            float a[4] = {a4.x, a4.y, a4.z, a4.w};
            float bb[4] = {b4.x, b4.y, b4.z, b4.w};
#pragma unroll
            for (int i = 0; i < 4; i++)
#pragma unroll
                for (int j = 0; j < 4; j++)
                    s[i][j] += a[i] * bb[j];
        }

        __syncthreads();

        const float sc = 0.125f;
#pragma unroll
        for (int i = 0; i < 4; i++) {
            int qg = qtile * 64 + ty * 4 + i;
#pragma unroll
            for (int j = 0; j < 4; j++) {
                int kg = kt * 64 + tx * 4 + j;
                s[i][j] = (kg <= qg) ? s[i][j] * sc : -1e30f;
            }
            float rm = fmaxf(fmaxf(s[i][0], s[i][1]), fmaxf(s[i][2], s[i][3]));
            rm = fmaxf(rm, __shfl_xor_sync(0xffffffffu, rm, 1));
            rm = fmaxf(rm, __shfl_xor_sync(0xffffffffu, rm, 2));
            rm = fmaxf(rm, __shfl_xor_sync(0xffffffffu, rm, 4));
            rm = fmaxf(rm, __shfl_xor_sync(0xffffffffu, rm, 8));
            float mnew = fmaxf(m_i[i], rm);
            float alpha = __expf(m_i[i] - mnew);
            m_i[i] = mnew;
            float rs = 0.f;
#pragma unroll
            for (int j = 0; j < 4; j++) {
                float p = __expf(s[i][j] - mnew);
                s[i][j] = p;
                rs += p;
            }
            rs += __shfl_xor_sync(0xffffffffu, rs, 1);
            rs += __shfl_xor_sync(0xffffffffu, rs, 2);
            rs += __shfl_xor_sync(0xffffffffu, rs, 4);
            rs += __shfl_xor_sync(0xffffffffu, rs, 8);
            l_i[i] = l_i[i] * alpha + rs;
#pragma unroll
            for (int j = 0; j < 4; j++) o_acc[i][j] *= alpha;
        }

#pragma unroll
        for (int i = 0; i < 4; i++)
            *(float4*)&Ps[ty * 4 + i][tx * 4] =
                make_float4(s[i][0], s[i][1], s[i][2], s[i][3]);
        __syncthreads();

#pragma unroll
        for (int kk = 0; kk < 64; kk++) {
            float4 v4 = *(const float4*)&Vs[kk][tx * 4];
            float a0 = Ps[ty * 4 + 0][kk];
            float a1 = Ps[ty * 4 + 1][kk];
            float a2 = Ps[ty * 4 + 2][kk];
            float a3 = Ps[ty * 4 + 3][kk];
            o_acc[0][0] += a0 * v4.x; o_acc[0][1] += a0 * v4.y;
            o_acc[0][2] += a0 * v4.z; o_acc[0][3] += a0 * v4.w;
            o_acc[1][0] += a1 * v4.x; o_acc[1][1] += a1 * v4.y;
            o_acc[1][2] += a1 * v4.z; o_acc[1][3] += a1 * v4.w;
            o_acc[2][0] += a2 * v4.x; o_acc[2][1] += a2 * v4.y;
            o_acc[2][2] += a2 * v4.z; o_acc[2][3] += a2 * v4.w;
            o_acc[3][0] += a3 * v4.x; o_acc[3][1] += a3 * v4.y;
            o_acc[3][2] += a3 * v4.z; o_acc[3][3] += a3 * v4.w;
        }
    }

#pragma unroll
    for (int i = 0; i < 4; i++) {
        float inv = 1.0f / l_i[i];
        int t = qtile * 64 + ty * 4 + i;
        float4 o4 = make_float4(o_acc[i][0] * inv, o_acc[i][1] * inv,
                                o_acc[i][2] * inv, o_acc[i][3] * inv);
        *(float4*)&g_att[(b * TDIM + t) * CDIM + h * HD + tx * 4] = o4;
    }
}

// ---------------------------------------------------------------------------
extern "C" void kernel_launch(void* const* d_in, const int* in_sizes, int n_in,
                              void* d_out, int out_size)
{
    const float* x     = (const float*)d_in[0];
    const float* Wqkv  = (const float*)d_in[1];
    const float* bqkv  = (const float*)d_in[2];
    const float* Wproj = (const float*)d_in[3];
    const float* bproj = (const float*)d_in[4];
    float* out = (float*)d_out;

    dim3 g1(NQKV / BN, MROWS / BM);      // 24 x 32
    gemm_qkv_kernel<<<g1, 256>>>(x, Wqkv, bqkv);

    dim3 ga(TDIM / 64, HN, BDIM);        // 32 x 16 x 2
    attn_kernel<<<ga, 256>>>();

    dim3 g2(CDIM / BN, MROWS / BM);      // 8 x 32
    gemm_proj_kernel<<<g2, 256>>>(Wproj, bproj, out);
}

// round 13
// speedup vs baseline: 1.8873x; 1.8873x over previous
#include <cuda_runtime.h>
#include <cuda_bf16.h>

// Problem constants (fixed by the reference setup)
#define BDIM 2
#define TDIM 2048
#define CDIM 1024
#define HN   16
#define HD   64
#define MROWS (BDIM * TDIM)   // 4096
#define NQKV  (3 * CDIM)      // 3072
#define KDEPTH CDIM           // 1024

// Scratch (static device globals — allocation-free). 64 MiB total, the exact
// footprint of the R3 run that passed the harness memory guard.
__device__ __align__(16) float g_Q[BDIM * HN * TDIM * HD];   // (B,H,T,hd) 16 MiB
__device__ __align__(16) float g_K[BDIM * HN * TDIM * HD];   // 16 MiB
__device__ __align__(16) float g_V[BDIM * HN * TDIM * HD];   // 16 MiB
__device__ __align__(16) float g_att[MROWS * CDIM];          // (B,T,C) 16 MiB

// ---------------------------------------------------------------------------
// SGEMM core: 128x128 block tile, BK=8, 256 threads, 8x8 per thread in
// 2x2 fragments of 4 (n at tx*4 and 64+tx*4; m at ty*4 and 64+ty*4).
// Register-prefetch of the next tile's LDG hides global latency.
// As plane padded to 132 words -> transpose stores hit 32 distinct banks.
// ---------------------------------------------------------------------------
__device__ __forceinline__ void sgemm_core(
    const float* __restrict__ A,   // [M,1024] row-major
    const float* __restrict__ W,   // [1024,ldw] row-major
    int ldw, int m0, int n0,
    float (*As)[132], float (*Bs)[128],
    float acc[2][2][4][4])
{
    const int tid = threadIdx.x;
    const int tx = tid & 15;
    const int ty = tid >> 4;

    const int arow = tid >> 1;            // 0..127
    const int ak = (tid & 1) * 4;         // 0 or 4
    const int brow = tid >> 5;            // 0..7
    const int bcol = (tid & 31) * 4;      // 0..124

#pragma unroll
    for (int mh = 0; mh < 2; mh++)
#pragma unroll
        for (int nh = 0; nh < 2; nh++)
#pragma unroll
            for (int i = 0; i < 4; i++)
#pragma unroll
                for (int j = 0; j < 4; j++) acc[mh][nh][i][j] = 0.f;

    const float* Ap = A + (m0 + arow) * KDEPTH + ak;
    const float* Wp = W + brow * ldw + n0 + bcol;

    float4 a = *(const float4*)Ap;
    float4 b = *(const float4*)Wp;

    for (int t = 0; t < KDEPTH / 8; t++) {
        // store current tile (A transposed)
        As[ak + 0][arow] = a.x;
        As[ak + 1][arow] = a.y;
        As[ak + 2][arow] = a.z;
        As[ak + 3][arow] = a.w;
        *(float4*)&Bs[brow][bcol] = b;
        __syncthreads();

        // prefetch next tile
        if (t < KDEPTH / 8 - 1) {
            a = *(const float4*)(Ap + (t + 1) * 8);
            b = *(const float4*)(Wp + (t + 1) * 8 * ldw);
        }

        // compute 8 k-steps
#pragma unroll
        for (int k = 0; k < 8; k++) {
            float4 am0 = *(const float4*)&As[k][ty * 4];
            float4 am1 = *(const float4*)&As[k][64 + ty * 4];
            float4 bn0 = *(const float4*)&Bs[k][tx * 4];
            float4 bn1 = *(const float4*)&Bs[k][64 + tx * 4];
            float am[2][4] = {{am0.x, am0.y, am0.z, am0.w},
                              {am1.x, am1.y, am1.z, am1.w}};
            float bn[2][4] = {{bn0.x, bn0.y, bn0.z, bn0.w},
                              {bn1.x, bn1.y, bn1.z, bn1.w}};
#pragma unroll
            for (int mh = 0; mh < 2; mh++)
#pragma unroll
                for (int nh = 0; nh < 2; nh++)
#pragma unroll
                    for (int i = 0; i < 4; i++)
#pragma unroll
                        for (int j = 0; j < 4; j++)
                            acc[mh][nh][i][j] += am[mh][i] * bn[nh][j];
        }
        __syncthreads();
    }
}

// ---------------------------------------------------------------------------
// GEMM 1: qkv = x @ Wqkv + bqkv ; scatter to Q/K/V (B,H,T,hd)  [R3 epilogue]
// ---------------------------------------------------------------------------
__global__ void __launch_bounds__(256) gemm_qkv_kernel(
    const float* __restrict__ A,      // x    [4096,1024]
    const float* __restrict__ W,      // Wqkv [1024,3072]
    const float* __restrict__ bias)   // bqkv [3072]
{
    __shared__ __align__(16) float As[8][132];
    __shared__ __align__(16) float Bs[8][128];

    const int m0 = blockIdx.y * 128;
    const int n0 = blockIdx.x * 128;
    const int tx = threadIdx.x & 15;
    const int ty = threadIdx.x >> 4;

    float acc[2][2][4][4];
    sgemm_core(A, W, NQKV, m0, n0, As, Bs, acc);

#pragma unroll
    for (int mh = 0; mh < 2; mh++) {
#pragma unroll
        for (int nh = 0; nh < 2; nh++) {
#pragma unroll
            for (int i = 0; i < 4; i++) {
                int m = m0 + mh * 64 + ty * 4 + i;
                int bb = m >> 11;
                int t = m & 2047;
#pragma unroll
                for (int j = 0; j < 4; j++) {
                    int n = n0 + nh * 64 + tx * 4 + j;
                    float c = acc[mh][nh][i][j] + bias[n];
                    int h = n / 192;
                    int r = n - h * 192;
                    int which = r >> 6;
                    int d = r & 63;
                    int idx = (((bb * HN + h) * TDIM) + t) * HD + d;
                    if (which == 0)      g_Q[idx] = c;
                    else if (which == 1) g_K[idx] = c;
                    else                 g_V[idx] = c;
                }
            }
        }
    }
}

// ---------------------------------------------------------------------------
// GEMM 2: out = att @ Wproj + bproj
// ---------------------------------------------------------------------------
__global__ void __launch_bounds__(256) gemm_proj_kernel(
    const float* __restrict__ W,      // Wproj [1024,1024]
    const float* __restrict__ bias,   // bproj [1024]
    float* __restrict__ out)          // [4096,1024]
{
    __shared__ __align__(16) float As[8][132];
    __shared__ __align__(16) float Bs[8][128];

    const int m0 = blockIdx.y * 128;
    const int n0 = blockIdx.x * 128;
    const int tx = threadIdx.x & 15;
    const int ty = threadIdx.x >> 4;

    float acc[2][2][4][4];
    sgemm_core(g_att, W, CDIM, m0, n0, As, Bs, acc);

#pragma unroll
    for (int mh = 0; mh < 2; mh++) {
#pragma unroll
        for (int nh = 0; nh < 2; nh++) {
#pragma unroll
            for (int i = 0; i < 4; i++) {
                int m = m0 + mh * 64 + ty * 4 + i;
#pragma unroll
                for (int j = 0; j < 4; j++) {
                    int n = n0 + nh * 64 + tx * 4 + j;
                    out[m * CDIM + n] = acc[mh][nh][i][j] + bias[n];
                }
            }
        }
    }
}

// ---------------------------------------------------------------------------
// Flash attention (fp32, causal) — byte-identical to the R3-validated kernel
// ---------------------------------------------------------------------------
__global__ void __launch_bounds__(256) attn_kernel()
{
    __shared__ __align__(16) float QsT[64][64];
    __shared__ __align__(16) float KsT[64][64];
    __shared__ __align__(16) float Vs[64][64];

    const int tid = threadIdx.x;
    const int tx = tid & 15;
    const int ty = tid >> 4;
    const int qtile = blockIdx.x;
    const int h = blockIdx.y;
    const int b = blockIdx.z;

    const float* Qb = g_Q + (((b * HN + h) * TDIM) + qtile * 64) * HD;
    const float* Kb = g_K + ((b * HN + h) * TDIM) * HD;
    const float* Vb = g_V + ((b * HN + h) * TDIM) * HD;

    {
        int row = tid >> 2;
        int d0 = (tid & 3) * 16;
#pragma unroll
        for (int v = 0; v < 4; v++) {
            float4 q4 = *(const float4*)&Qb[row * HD + d0 + v * 4];
            QsT[d0 + v * 4 + 0][row] = q4.x;
            QsT[d0 + v * 4 + 1][row] = q4.y;
            QsT[d0 + v * 4 + 2][row] = q4.z;
            QsT[d0 + v * 4 + 3][row] = q4.w;
        }
    }

    float m_i[4], l_i[4], o_acc[4][4];
#pragma unroll
    for (int i = 0; i < 4; i++) {
        m_i[i] = -1e30f;
        l_i[i] = 0.f;
#pragma unroll
        for (int j = 0; j < 4; j++) o_acc[i][j] = 0.f;
    }

    float (*Ps)[64] = (float (*)[64])KsT;

    for (int kt = 0; kt <= qtile; kt++) {
        __syncthreads();
        {
            int row = tid >> 2;
            int d0 = (tid & 3) * 16;
            const float* Kp = Kb + (kt * 64 + row) * HD;
            const float* Vp = Vb + (kt * 64 + row) * HD;
#pragma unroll
            for (int v = 0; v < 4; v++) {
                float4 k4 = *(const float4*)&Kp[d0 + v * 4];
                KsT[d0 + v * 4 + 0][row] = k4.x;
                KsT[d0 + v * 4 + 1][row] = k4.y;
                KsT[d0 + v * 4 + 2][row] = k4.z;
                KsT[d0 + v * 4 + 3][row] = k4.w;
                *(float4*)&Vs[row][d0 + v * 4] = *(const float4*)&Vp[d0 + v * 4];
            }
        }
        __syncthreads();

        float s[4][4] = {};
#pragma unroll
        for (int d = 0; d < 64; d++) {
            float4 a4 = *(const float4*)&QsT[d][ty * 4];
            float4 b4 = *(const float4*)&KsT[d][tx * 4];
            float a[4] = {a4.x, a4.y, a4.z, a4.w};
            float bb[4] = {b4.x, b4.y, b4.z, b4.w};
#pragma unroll
            for (int i = 0; i < 4; i++)
#pragma unroll
                for (int j = 0; j < 4; j++)
                    s[i][j] += a[i] * bb[j];
        }

        __syncthreads();

        const float sc = 0.125f;
#pragma unroll
        for (int i = 0; i < 4; i++) {
            int qg = qtile * 64 + ty * 4 + i;
#pragma unroll
            for (int j = 0; j < 4; j++) {
                int kg = kt * 64 + tx * 4 + j;
                s[i][j] = (kg <= qg) ? s[i][j] * sc : -1e30f;
            }
            float rm = fmaxf(fmaxf(s[i][0], s[i][1]), fmaxf(s[i][2], s[i][3]));
            rm = fmaxf(rm, __shfl_xor_sync(0xffffffffu, rm, 1));
            rm = fmaxf(rm, __shfl_xor_sync(0xffffffffu, rm, 2));
            rm = fmaxf(rm, __shfl_xor_sync(0xffffffffu, rm, 4));
            rm = fmaxf(rm, __shfl_xor_sync(0xffffffffu, rm, 8));
            float mnew = fmaxf(m_i[i], rm);
            float alpha = __expf(m_i[i] - mnew);
            m_i[i] = mnew;
            float rs = 0.f;
#pragma unroll
            for (int j = 0; j < 4; j++) {
                float p = __expf(s[i][j] - mnew);
                s[i][j] = p;
                rs += p;
            }
            rs += __shfl_xor_sync(0xffffffffu, rs, 1);
            rs += __shfl_xor_sync(0xffffffffu, rs, 2);
            rs += __shfl_xor_sync(0xffffffffu, rs, 4);
            rs += __shfl_xor_sync(0xffffffffu, rs, 8);
            l_i[i] = l_i[i] * alpha + rs;
#pragma unroll
            for (int j = 0; j < 4; j++) o_acc[i][j] *= alpha;
        }

#pragma unroll
        for (int i = 0; i < 4; i++)
            *(float4*)&Ps[ty * 4 + i][tx * 4] =
                make_float4(s[i][0], s[i][1], s[i][2], s[i][3]);
        __syncthreads();

#pragma unroll
        for (int kk = 0; kk < 64; kk++) {
            float4 v4 = *(const float4*)&Vs[kk][tx * 4];
            float a0 = Ps[ty * 4 + 0][kk];
            float a1 = Ps[ty * 4 + 1][kk];
            float a2 = Ps[ty * 4 + 2][kk];
            float a3 = Ps[ty * 4 + 3][kk];
            o_acc[0][0] += a0 * v4.x; o_acc[0][1] += a0 * v4.y;
            o_acc[0][2] += a0 * v4.z; o_acc[0][3] += a0 * v4.w;
            o_acc[1][0] += a1 * v4.x; o_acc[1][1] += a1 * v4.y;
            o_acc[1][2] += a1 * v4.z; o_acc[1][3] += a1 * v4.w;
            o_acc[2][0] += a2 * v4.x; o_acc[2][1] += a2 * v4.y;
            o_acc[2][2] += a2 * v4.z; o_acc[2][3] += a2 * v4.w;
            o_acc[3][0] += a3 * v4.x; o_acc[3][1] += a3 * v4.y;
            o_acc[3][2] += a3 * v4.z; o_acc[3][3] += a3 * v4.w;
        }
    }

#pragma unroll
    for (int i = 0; i < 4; i++) {
        float inv = 1.0f / l_i[i];
        int t = qtile * 64 + ty * 4 + i;
        float4 o4 = make_float4(o_acc[i][0] * inv, o_acc[i][1] * inv,
                                o_acc[i][2] * inv, o_acc[i][3] * inv);
        *(float4*)&g_att[(b * TDIM + t) * CDIM + h * HD + tx * 4] = o4;
    }
}

// ---------------------------------------------------------------------------
extern "C" void kernel_launch(void* const* d_in, const int* in_sizes, int n_in,
                              void* d_out, int out_size)
{
    const float* x     = (const float*)d_in[0];
    const float* Wqkv  = (const float*)d_in[1];
    const float* bqkv  = (const float*)d_in[2];
    const float* Wproj = (const float*)d_in[3];
    const float* bproj = (const float*)d_in[4];
    float* out = (float*)d_out;

    dim3 g1(NQKV / 128, MROWS / 128);    // 24 x 32
    gemm_qkv_kernel<<<g1, 256>>>(x, Wqkv, bqkv);

    dim3 ga(TDIM / 64, HN, BDIM);        // 32 x 16 x 2
    attn_kernel<<<ga, 256>>>();

    dim3 g2(CDIM / 128, MROWS / 128);    // 8 x 32
    gemm_proj_kernel<<<g2, 256>>>(Wproj, bproj, out);
}